// round 15
// baseline (speedup 1.0000x reference)
#include <cuda_runtime.h>
#include <cuda_bf16.h>
#include <math.h>

#define BB 2
#define NN 8192
#define KK 30
#define NODES (BB*NN)
#define DIM 148

// ---------------- scratch ----------------
__device__ float g_vhV[NODES * 96];
__device__ float g_sV1[NODES * 100];
__device__ float g_hm [NODES * DIM];
__device__ float g_t4 [NODES * 496];

__device__ __forceinline__ float f4c(const float4& v, int q) {
    return q == 0 ? v.x : q == 1 ? v.y : q == 2 ? v.z : v.w;
}
__device__ __forceinline__ unsigned tf32u(float f) {
    unsigned u;
    asm("cvt.rna.tf32.f32 %0, %1;" : "=r"(u) : "f"(f));
    return u;
}
__device__ __forceinline__ float tf32f(float f) { return __uint_as_float(tf32u(f)); }

__device__ __forceinline__ void mma8(float c[4], const unsigned a[4], unsigned b0, unsigned b1) {
    asm volatile(
        "mma.sync.aligned.m16n8k8.row.col.f32.tf32.tf32.f32 "
        "{%0,%1,%2,%3}, {%4,%5,%6,%7}, {%8,%9}, {%0,%1,%2,%3};"
        : "+f"(c[0]), "+f"(c[1]), "+f"(c[2]), "+f"(c[3])
        : "r"(a[0]), "r"(a[1]), "r"(a[2]), "r"(a[3]), "r"(b0), "r"(b1));
}

// =================================================================
// Kernel 0: per-node precompute
// =================================================================
#define P_W 10000
#define PRE_SMEM ((P_W + 8*200) * 4)

__global__ __launch_bounds__(256, 1)
void pre_kernel(const float* __restrict__ hV,
                const float* __restrict__ Wh1,
                const float* __restrict__ Ws1,
                const float* __restrict__ bs1)
{
    extern __shared__ float sm[];
    const int tid = threadIdx.x, w = tid >> 5, lane = tid & 31;
    for (int i = tid; i < P_W; i += 256) sm[i] = __ldg(&Ws1[i]);
    __syncthreads();
    float* xw = sm + P_W + w * 200;

    for (long base = (long)blockIdx.x * 16; base < NODES; base += (long)gridDim.x * 16) {
        long n0 = base + w * 2, n1 = n0 + 1;
        bool ok0 = n0 < NODES, ok1 = n1 < NODES;
        const float* hv0 = hV + (ok0 ? n0 : 0) * DIM;
        const float* hv1 = hV + (ok1 ? n1 : 0) * DIM;

#pragma unroll
        for (int e = 0; e < 2; e++) {
            const float* hv = e ? hv1 : hv0;
            float a0 = 0.f, a1 = 0.f, a2 = 0.f;
#pragma unroll
            for (int i = 0; i < 16; i++) {
                float wt = __ldg(&Wh1[i * 32 + lane]);
                a0 = fmaf(hv[3*i+0], wt, a0);
                a1 = fmaf(hv[3*i+1], wt, a1);
                a2 = fmaf(hv[3*i+2], wt, a2);
            }
            bool ok = e ? ok1 : ok0;
            long n = e ? n1 : n0;
            if (ok) {
                g_vhV[n*96 + lane*3 + 0] = a0;
                g_vhV[n*96 + lane*3 + 1] = a1;
                g_vhV[n*96 + lane*3 + 2] = a2;
            }
        }

        for (int t = lane; t < 100; t += 32) { xw[t] = hv0[48+t]; xw[100+t] = hv1[48+t]; }
        __syncwarp();

        int jc[4]; float a0[4], a1[4];
#pragma unroll
        for (int jj = 0; jj < 4; jj++) {
            int j = jj*32 + lane; jc[jj] = j < 100 ? j : 99;
            float v = __ldg(&bs1[jc[jj]]);
            a0[jj] = v; a1[jj] = v;
        }
        const float4* x0 = (const float4*)xw;
        const float4* x1 = (const float4*)(xw + 100);
#pragma unroll 2
        for (int i4 = 0; i4 < 25; i4++) {
            float4 va = x0[i4], vb = x1[i4];
            const float* wr = sm + i4 * 400;
#pragma unroll
            for (int q = 0; q < 4; q++) {
                float fa = f4c(va,q), fb = f4c(vb,q);
                const float* wq = wr + q * 100;
#pragma unroll
                for (int jj = 0; jj < 4; jj++) {
                    float wt = wq[jc[jj]];
                    a0[jj] = fmaf(fa, wt, a0[jj]);
                    a1[jj] = fmaf(fb, wt, a1[jj]);
                }
            }
        }
#pragma unroll
        for (int jj = 0; jj < 4; jj++) {
            int j = jj*32 + lane;
            if (j < 100) {
                if (ok0) g_sV1[n0*100 + j] = a0[jj];
                if (ok1) g_sV1[n1*100 + j] = a1[jj];
            }
        }
        __syncwarp();
    }
}

// =================================================================
// Edge kernel: R11 form (known good)
// =================================================================
#define O_W1    0        // [136][104] tf32 (Ws1 rows 100..231)
#define O_W2    14144    // [120][104]
#define O_W3    26624    // [120][104]
#define O_WH1S  39104    // [16][40]
#define O_WV1S  39744    // [32][24]
#define O_WH2S  40512    // [16][24]
#define O_WV2S  40896
#define O_WH3S  41280
#define O_WV3S  41664
#define O_BS2   42048    // 100
#define O_BS3   42148    // 100
#define O_PVH   42248    // 96
#define O_PRS   42344    // 100
#define O_ACC   42444    // 148
#define O_MK    42592    // 32
#define O_VA    42624    // [96][20]
#define O_VB    44544    // [96][36]
#define O_X1    48000    // [32][140] (X3 aliases, stride 124)
#define O_X2    52480    // [32][124] (z/zv reuse)
#define O_HV    56448    // 148
#define SM_FLOATS 56596
#define EDGE_SMEM (SM_FLOATS * 4)

#define XS1 140
#define XS2 124
#define WS  104
#define VAS 20
#define VBS 36

__device__ __forceinline__ void mma_stage(const unsigned* __restrict__ X, int XS,
                                          const unsigned* __restrict__ Wm, int KT,
                                          int gid, int tig, int w, float C[2][2][4])
{
    const bool nt1ok = (2*w+1) < 13;
    const int col0 = 8*(2*w) + gid;
    const int col1 = nt1ok ? (8*(2*w+1) + gid) : col0;
#pragma unroll 2
    for (int kt = 0; kt < KT; kt++) {
        const int k0 = kt * 8;
        unsigned a[2][4];
#pragma unroll
        for (int mt = 0; mt < 2; mt++) {
            const unsigned* xr = X + (16*mt + gid)*XS + k0 + tig;
            a[mt][0] = xr[0];
            a[mt][1] = xr[8*XS];
            a[mt][2] = xr[4];
            a[mt][3] = xr[8*XS + 4];
        }
        const unsigned* wr = Wm + (k0 + tig)*WS;
        unsigned b00 = wr[col0], b01 = wr[4*WS + col0];
        unsigned b10 = wr[col1], b11 = wr[4*WS + col1];
#pragma unroll
        for (int mt = 0; mt < 2; mt++) {
            mma8(C[mt][0], a[mt], b00, b01);
            if (nt1ok) mma8(C[mt][1], a[mt], b10, b11);
        }
    }
}

__device__ __forceinline__ void store_stage(float* __restrict__ Xo, int XSo,
                                            const float* __restrict__ addend,
                                            const float C[2][2][4],
                                            int gid, int tig, int w)
{
#pragma unroll
    for (int mt = 0; mt < 2; mt++)
#pragma unroll
    for (int nti = 0; nti < 2; nti++) {
        int nt = 2*w + nti;
        if (nt >= 13) continue;
#pragma unroll
        for (int r = 0; r < 4; r++) {
            int edge = 16*mt + gid + ((r >> 1) << 3);
            int n = 8*nt + 2*tig + (r & 1);
            if (edge < 30 && n < 100)
                Xo[edge*XSo + n] = tf32f(fmaxf(C[mt][nti][r] + addend[n], 0.f));
        }
    }
}

__device__ __forceinline__ void mma_tile(const unsigned* __restrict__ A, int AS,
                                         const unsigned* __restrict__ Bw, int BS,
                                         int KT, int mt, int nt,
                                         int gid, int tig, float C[4])
{
#pragma unroll 2
    for (int kt = 0; kt < KT; kt++) {
        const unsigned* xr = A + (16*mt + gid)*AS + kt*8 + tig;
        unsigned a[4] = { xr[0], xr[8*AS], xr[4], xr[8*AS + 4] };
        const unsigned* wr = Bw + (kt*8 + tig)*BS;
        mma8(C, a, wr[8*nt + gid], wr[4*BS + 8*nt + gid]);
    }
}

__global__ __launch_bounds__(512, 1)
void edge_kernel(const float* __restrict__ hM, const int* __restrict__ maskA,
                 const float* __restrict__ hV,
                 const float* __restrict__ lng, const float* __restrict__ lnb,
                 const float* __restrict__ Wh1, const float* __restrict__ Wv1,
                 const float* __restrict__ Ws1,
                 const float* __restrict__ Wh2, const float* __restrict__ Wv2,
                 const float* __restrict__ Ws2, const float* __restrict__ bs2,
                 const float* __restrict__ Wh3, const float* __restrict__ Wv3,
                 const float* __restrict__ Ws3, const float* __restrict__ bs3)
{
    extern __shared__ float sm[];
    unsigned* usm = (unsigned*)sm;
    const int tid = threadIdx.x, w = tid >> 5, lane = tid & 31;
    const int gid = lane >> 2, tig = lane & 3;

    // ---- one-time weight fills ----
    for (int i = tid; i < 136*WS; i += 512) {
        int k = i / WS, n = i - k*WS;
        sm[O_W1+i] = (k < 132 && n < 100) ? tf32f(__ldg(&Ws1[(100+k)*100 + n])) : 0.f;
    }
    for (int i = tid; i < 120*WS; i += 512) {
        int k = i / WS, n = i - k*WS;
        sm[O_W2+i] = (k < 116 && n < 100) ? tf32f(__ldg(&Ws2[k*100 + n])) : 0.f;
        sm[O_W3+i] = (k < 116 && n < 100) ? tf32f(__ldg(&Ws3[k*100 + n])) : 0.f;
    }
    for (int i = tid; i < 512; i += 512) {
        int k = i >> 5, n = i & 31;
        sm[O_WH1S + k*40 + n] = tf32f(__ldg(&Wh1[(16+k)*32 + n]));
    }
    if (tid < 512) {
        int k = tid >> 4, n = tid & 15;
        sm[O_WV1S + k*24 + n] = tf32f(__ldg(&Wv1[k*16 + n]));
    }
    if (tid < 256) {
        int k = tid >> 4, n = tid & 15;
        sm[O_WH2S + k*24 + n] = tf32f(__ldg(&Wh2[tid]));
        sm[O_WV2S + k*24 + n] = tf32f(__ldg(&Wv2[tid]));
        sm[O_WH3S + k*24 + n] = tf32f(__ldg(&Wh3[tid]));
        sm[O_WV3S + k*24 + n] = tf32f(__ldg(&Wv3[tid]));
    }
    if (tid < 100) { sm[O_BS2+tid] = __ldg(&bs2[tid]); sm[O_BS3+tid] = __ldg(&bs3[tid]); }
    for (int i = tid; i < 32*XS2; i += 512) sm[O_X2+i] = 0.f;
    for (int i = tid; i < 2*XS1;  i += 512) sm[O_X1 + 30*XS1 + i] = 0.f;
    for (int i = tid; i < 30*8;   i += 512) sm[O_X1 + (i>>3)*XS1 + 132 + (i&7)] = 0.f;

    // ---- prefetch setup ----
    int soff[9]; bool sval[9];
#pragma unroll
    for (int r = 0; r < 9; r++) {
        int idx = tid + r*512;
        sval[r] = idx < KK*DIM;
        int ii = sval[r] ? idx : 0;
        int e = ii / DIM, t = ii - e*DIM;
        soff[r] = (t < 48) ? (O_VA + (3*e + t%3)*VAS + t/3)
                           : (O_X1 + e*XS1 + (t-48));
    }
    float R[9]; int mkR = 0; float pvhR = 0.f, prsR = 0.f, hvR = 0.f;

    {   // prologue prefetch
        long n = blockIdx.x;
        const float* src = hM + n*KK*DIM;
#pragma unroll
        for (int r = 0; r < 9; r++) if (sval[r]) R[r] = __ldg(&src[tid + r*512]);
        if (tid < 30)  mkR  = __ldg(&maskA[n*KK + tid]);
        if (tid < 96)  pvhR = g_vhV[n*96 + tid];
        if (tid < 100) prsR = g_sV1[n*100 + tid];
        if (tid < 148) hvR  = __ldg(&hV[n*DIM + tid]);
    }
    __syncthreads();

    for (long node = blockIdx.x; node < NODES; node += gridDim.x) {
        // ---- P0: scatter prefetched data ----
#pragma unroll
        for (int r = 0; r < 9; r++) if (sval[r]) sm[soff[r]] = tf32f(R[r]);
        if (tid < 30)  sm[O_MK + tid]  = (float)mkR;
        if (tid < 96)  sm[O_PVH + tid] = pvhR;
        if (tid < 100) sm[O_PRS + tid] = prsR;
        if (tid < 148) sm[O_HV + tid]  = hvR;
        __syncthreads();

        // prefetch next node
        {
            long nn = node + gridDim.x;
            long n = (nn < NODES) ? nn : node;
            const float* src = hM + n*KK*DIM;
#pragma unroll
            for (int r = 0; r < 9; r++) if (sval[r]) R[r] = __ldg(&src[tid + r*512]);
            if (tid < 30)  mkR  = __ldg(&maskA[n*KK + tid]);
            if (tid < 96)  pvhR = g_vhV[n*96 + tid];
            if (tid < 100) prsR = g_sV1[n*100 + tid];
            if (tid < 148) hvR  = __ldg(&hV[n*DIM + tid]);
        }

        // ---- P1: vh1 MMA (24 tiles) ----
        for (int t = w; t < 24; t += 16) {
            int mt = t % 6, nt = t / 6;
            float C[4] = {};
            mma_tile(usm + O_VA, VAS, usm + O_WH1S, 40, 2, mt, nt, gid, tig, C);
#pragma unroll
            for (int r = 0; r < 4; r++) {
                int row = 16*mt + gid + 8*(r>>1);
                int n = 8*nt + 2*tig + (r&1);
                sm[O_VB + row*VBS + n] = tf32f(C[r] + sm[O_PVH + n*3 + (row%3)]);
            }
        }
        __syncthreads();

        // ---- P2: vn1 -> X1 cols 100..131 ----
        for (int v = tid; v < 960; v += 512) {
            int e = v >> 5, h = v & 31;
            float x0 = sm[O_VB + (3*e+0)*VBS + h];
            float x1 = sm[O_VB + (3*e+1)*VBS + h];
            float x2 = sm[O_VB + (3*e+2)*VBS + h];
            sm[O_X1 + e*XS1 + 100 + h] = tf32f(sqrtf(fmaf(x0,x0,fmaf(x1,x1,x2*x2)) + 1e-8f));
        }
        __syncthreads();

        // ---- P3: s1 MMA (w<7) || v1 MMA (w>=7) ----
        if (w < 7) {
            float C[2][2][4] = {};
            mma_stage(usm + O_X1, XS1, usm + O_W1, 17, gid, tig, w, C);
            store_stage(sm + O_X2, XS2, sm + O_PRS, C, gid, tig, w);
        } else {
            for (int t = w - 7; t < 12; t += 9) {
                int mt = t % 6, nt = t / 6;
                float C[4] = {};
                mma_tile(usm + O_VB, VBS, usm + O_WV1S, 24, 4, mt, nt, gid, tig, C);
#pragma unroll
                for (int r = 0; r < 4; r++) {
                    int row = 16*mt + gid + 8*(r>>1);
                    int n = 8*nt + 2*tig + (r&1);
                    sm[O_VA + row*VAS + n] = C[r];
                }
            }
        }
        __syncthreads();

        // ---- P4: gate v1 ----
        if (tid < 480) {
            int e = tid >> 4, h = tid & 15;
            float x0 = sm[O_VA + (3*e+0)*VAS + h];
            float x1 = sm[O_VA + (3*e+1)*VAS + h];
            float x2 = sm[O_VA + (3*e+2)*VAS + h];
            float nr = sqrtf(fmaf(x0,x0,fmaf(x1,x1,x2*x2)) + 1e-8f);
            float g = 1.f / (1.f + __expf(-nr));
            sm[O_VA + (3*e+0)*VAS + h] = tf32f(x0*g);
            sm[O_VA + (3*e+1)*VAS + h] = tf32f(x1*g);
            sm[O_VA + (3*e+2)*VAS + h] = tf32f(x2*g);
        }
        __syncthreads();

        // ---- P5: vh2 MMA (12 tiles) ----
        for (int t = w; t < 12; t += 16) {
            int mt = t % 6, nt = t / 6;
            float C[4] = {};
            mma_tile(usm + O_VA, VAS, usm + O_WH2S, 24, 2, mt, nt, gid, tig, C);
#pragma unroll
            for (int r = 0; r < 4; r++) {
                int row = 16*mt + gid + 8*(r>>1);
                int n = 8*nt + 2*tig + (r&1);
                sm[O_VB + row*VBS + n] = tf32f(C[r]);
            }
        }
        __syncthreads();

        // ---- P6: vn2 -> X2 cols 100..115 ----
        if (tid < 480) {
            int e = tid >> 4, h = tid & 15;
            float x0 = sm[O_VB + (3*e+0)*VBS + h];
            float x1 = sm[O_VB + (3*e+1)*VBS + h];
            float x2 = sm[O_VB + (3*e+2)*VBS + h];
            sm[O_X2 + e*XS2 + 100 + h] = tf32f(sqrtf(fmaf(x0,x0,fmaf(x1,x1,x2*x2)) + 1e-8f));
        }
        __syncthreads();

        // ---- P7: s2 MMA (w<7) || v2 MMA (w>=7) ----
        if (w < 7) {
            float C[2][2][4] = {};
            mma_stage(usm + O_X2, XS2, usm + O_W2, 15, gid, tig, w, C);
            store_stage(sm + O_X1, XS2, sm + O_BS2, C, gid, tig, w);   // X3 = X1 space
        } else {
            for (int t = w - 7; t < 12; t += 9) {
                int mt = t % 6, nt = t / 6;
                float C[4] = {};
                mma_tile(usm + O_VB, VBS, usm + O_WV2S, 24, 2, mt, nt, gid, tig, C);
#pragma unroll
                for (int r = 0; r < 4; r++) {
                    int row = 16*mt + gid + 8*(r>>1);
                    int n = 8*nt + 2*tig + (r&1);
                    sm[O_VA + row*VAS + n] = C[r];
                }
            }
        }
        __syncthreads();

        // ---- P8: gate v2 ----
        if (tid < 480) {
            int e = tid >> 4, h = tid & 15;
            float x0 = sm[O_VA + (3*e+0)*VAS + h];
            float x1 = sm[O_VA + (3*e+1)*VAS + h];
            float x2 = sm[O_VA + (3*e+2)*VAS + h];
            float nr = sqrtf(fmaf(x0,x0,fmaf(x1,x1,x2*x2)) + 1e-8f);
            float g = 1.f / (1.f + __expf(-nr));
            sm[O_VA + (3*e+0)*VAS + h] = tf32f(x0*g);
            sm[O_VA + (3*e+1)*VAS + h] = tf32f(x1*g);
            sm[O_VA + (3*e+2)*VAS + h] = tf32f(x2*g);
        }
        __syncthreads();

        // ---- P9: vh3 MMA ----
        for (int t = w; t < 12; t += 16) {
            int mt = t % 6, nt = t / 6;
            float C[4] = {};
            mma_tile(usm + O_VA, VAS, usm + O_WH3S, 24, 2, mt, nt, gid, tig, C);
#pragma unroll
            for (int r = 0; r < 4; r++) {
                int row = 16*mt + gid + 8*(r>>1);
                int n = 8*nt + 2*tig + (r&1);
                sm[O_VB + row*VBS + n] = tf32f(C[r]);
            }
        }
        __syncthreads();

        // ---- P10: vn3 -> X3 cols 100..115 ----
        if (tid < 480) {
            int e = tid >> 4, h = tid & 15;
            float x0 = sm[O_VB + (3*e+0)*VBS + h];
            float x1 = sm[O_VB + (3*e+1)*VBS + h];
            float x2 = sm[O_VB + (3*e+2)*VBS + h];
            sm[O_X1 + e*XS2 + 100 + h] = tf32f(sqrtf(fmaf(x0,x0,fmaf(x1,x1,x2*x2)) + 1e-8f));
        }
        __syncthreads();

        // ---- P11: linearized stage 3 — masked sums ----
        if (tid < 116) {
            float s = 0.f;
#pragma unroll 5
            for (int e = 0; e < 30; e++)
                s = fmaf(sm[O_MK + e], sm[O_X1 + e*XS2 + tid], s);
            sm[O_X2 + tid] = s;
        } else if (tid >= 128 && tid < 176) {
            int i = tid - 128;
            int h = i / 3, c = i - 3*h;
            float s = 0.f;
#pragma unroll 5
            for (int e = 0; e < 30; e++)
                s = fmaf(sm[O_MK + e], sm[O_VB + (3*e+c)*VBS + h], s);
            sm[O_X2 + 128 + i] = s;
        }
        __syncthreads();

        // ---- P12: tiny matvecs ----
        if (tid < 100) {
            float acc = 0.f;
#pragma unroll 4
            for (int k = 0; k < 116; k++)
                acc = fmaf(sm[O_X2 + k], sm[O_W3 + k*WS + tid], acc);
            sm[O_ACC + 48 + tid] = acc;
        } else if (tid >= 128 && tid < 176) {
            int i = tid - 128;
            int o = i / 3, c = i - 3*o;
            float acc = 0.f;
#pragma unroll
            for (int h = 0; h < 16; h++)
                acc = fmaf(sm[O_X2 + 128 + h*3 + c], sm[O_WV3S + h*24 + o], acc);
            sm[O_ACC + 3*o + c] = acc;
        }
        __syncthreads();

        // ---- P13: ln0 -> g_hm ----
        if (w == 0) {
            float smk = (lane < 30) ? sm[O_MK + lane] : 0.f;
#pragma unroll
            for (int o = 16; o; o >>= 1) smk += __shfl_xor_sync(0xffffffffu, smk, o);

            const float inv30 = 1.f / 30.f;
            float v0=0.f, v1=0.f, v2=0.f, q=0.f;
            if (lane < 16) {
                v0 = sm[O_HV + 3*lane+0] + sm[O_ACC + 3*lane+0] * inv30;
                v1 = sm[O_HV + 3*lane+1] + sm[O_ACC + 3*lane+1] * inv30;
                v2 = sm[O_HV + 3*lane+2] + sm[O_ACC + 3*lane+2] * inv30;
                q = fmaf(v0,v0,fmaf(v1,v1,v2*v2));
            }
#pragma unroll
            for (int o = 16; o; o >>= 1) q += __shfl_xor_sync(0xffffffffu, q, o);
            float dinv = rsqrtf(q * (1.f/16.f) + 1e-8f);

            float s[4]; float sum = 0.f, sq = 0.f;
#pragma unroll
            for (int jj = 0; jj < 4; jj++) {
                int j = jj*32 + lane;
                s[jj] = (j < 100)
                    ? (sm[O_HV + 48+j] + (sm[O_ACC + 48 + j] + sm[O_BS3+j]*smk) * inv30) : 0.f;
                sum += s[jj]; sq = fmaf(s[jj], s[jj], sq);
            }
#pragma unroll
            for (int o = 16; o; o >>= 1) {
                sum += __shfl_xor_sync(0xffffffffu, sum, o);
                sq  += __shfl_xor_sync(0xffffffffu, sq,  o);
            }
            float mu  = sum * 0.01f;
            float var = sq * 0.01f - mu*mu;
            float inv = rsqrtf(var + 1e-5f);

            float* o = g_hm + (long)node * DIM;
            if (lane < 16) {
                o[3*lane+0] = v0*dinv; o[3*lane+1] = v1*dinv; o[3*lane+2] = v2*dinv;
            }
#pragma unroll
            for (int jj = 0; jj < 4; jj++) {
                int j = jj*32 + lane;
                if (j < 100) o[48+j] = (s[jj]-mu)*inv*__ldg(&lng[j]) + __ldg(&lnb[j]);
            }
        }
        __syncthreads();
    }
}

// =================================================================
// Kernel 3: gvp4 — 512 threads, float4 weight loads (contiguous cols)
// =================================================================
#define G4_W 52800
#define G4_SMEM ((G4_W + 16*264) * 4)   // 228096 B

__global__ __launch_bounds__(512, 1)
void gvp4_kernel(const float* __restrict__ Wh4, const float* __restrict__ Wv4,
                 const float* __restrict__ Ws4, const float* __restrict__ bs4)
{
    extern __shared__ float sm[];
    const int tid = threadIdx.x, w = tid >> 5, lane = tid & 31;
    for (int i = tid; i < G4_W; i += 512) sm[i] = __ldg(&Ws4[i]);
    __syncthreads();
    float* xw = sm + G4_W + w * 264;
    const int tl = lane & 3;   // tail lane id

    for (long base = (long)blockIdx.x * 32; base < NODES; base += (long)gridDim.x * 32) {
        long n0 = base + w*2, n1 = n0 + 1;
        bool ok0 = n0 < NODES, ok1 = n1 < NODES;
        const float* h0 = g_hm + (ok0 ? n0 : 0) * DIM;
        const float* h1 = g_hm + (ok1 ? n1 : 0) * DIM;

        float A[2][3], vn[2];
#pragma unroll
        for (int e = 0; e < 2; e++) {
            const float* h = e ? h1 : h0;
            float a0=0.f, a1=0.f, a2=0.f;
#pragma unroll
            for (int i = 0; i < 16; i++) {
                float wt = __ldg(&Wh4[i*32 + lane]);
                a0 = fmaf(h[3*i+0], wt, a0);
                a1 = fmaf(h[3*i+1], wt, a1);
                a2 = fmaf(h[3*i+2], wt, a2);
            }
            A[e][0]=a0; A[e][1]=a1; A[e][2]=a2;
            vn[e] = sqrtf(fmaf(a0,a0,fmaf(a1,a1,a2*a2)) + 1e-8f);
        }
        for (int t = lane; t < 100; t += 32) { xw[t] = h0[48+t]; xw[132+t] = h1[48+t]; }
        xw[100+lane] = vn[0]; xw[232+lane] = vn[1];
        __syncwarp();

        // columns: 3 float4 groups at 4*lane + 128*g, plus tail 384+4*tl (lanes 0..3 store)
        float acc0[3][4], acc1[3][4], t0a[4], t1a[4];
#pragma unroll
        for (int g = 0; g < 3; g++) {
            const float4 bv = *(const float4*)(bs4 + 4*lane + 128*g);
            acc0[g][0]=bv.x; acc0[g][1]=bv.y; acc0[g][2]=bv.z; acc0[g][3]=bv.w;
            acc1[g][0]=bv.x; acc1[g][1]=bv.y; acc1[g][2]=bv.z; acc1[g][3]=bv.w;
        }
        {
            const float4 bv = *(const float4*)(bs4 + 384 + 4*tl);
            t0a[0]=bv.x; t0a[1]=bv.y; t0a[2]=bv.z; t0a[3]=bv.w;
            t1a[0]=bv.x; t1a[1]=bv.y; t1a[2]=bv.z; t1a[3]=bv.w;
        }
        const float4* x0 = (const float4*)xw;
        const float4* x1 = (const float4*)(xw + 132);
        for (int i4 = 0; i4 < 33; i4++) {
            float4 va = x0[i4], vb = x1[i4];
            const float* wr = sm + i4 * 1600;
#pragma unroll
            for (int q = 0; q < 4; q++) {
                float fa = f4c(va,q), fb = f4c(vb,q);
                const float* wq = wr + q * 400;
#pragma unroll
                for (int g = 0; g < 3; g++) {
                    const float4 wv = *(const float4*)(wq + 4*lane + 128*g);
                    acc0[g][0] = fmaf(fa, wv.x, acc0[g][0]);
                    acc0[g][1] = fmaf(fa, wv.y, acc0[g][1]);
                    acc0[g][2] = fmaf(fa, wv.z, acc0[g][2]);
                    acc0[g][3] = fmaf(fa, wv.w, acc0[g][3]);
                    acc1[g][0] = fmaf(fb, wv.x, acc1[g][0]);
                    acc1[g][1] = fmaf(fb, wv.y, acc1[g][1]);
                    acc1[g][2] = fmaf(fb, wv.z, acc1[g][2]);
                    acc1[g][3] = fmaf(fb, wv.w, acc1[g][3]);
                }
                {
                    const float4 wv = *(const float4*)(wq + 384 + 4*tl);
                    t0a[0] = fmaf(fa, wv.x, t0a[0]);
                    t0a[1] = fmaf(fa, wv.y, t0a[1]);
                    t0a[2] = fmaf(fa, wv.z, t0a[2]);
                    t0a[3] = fmaf(fa, wv.w, t0a[3]);
                    t1a[0] = fmaf(fb, wv.x, t1a[0]);
                    t1a[1] = fmaf(fb, wv.y, t1a[1]);
                    t1a[2] = fmaf(fb, wv.z, t1a[2]);
                    t1a[3] = fmaf(fb, wv.w, t1a[3]);
                }
            }
        }

        // v part + output
#pragma unroll
        for (int e = 0; e < 2; e++) {
            float b0=0.f, b1=0.f, b2=0.f;
#pragma unroll
            for (int hh = 0; hh < 32; hh++) {
                float wt = __ldg(&Wv4[hh*32 + lane]);
                b0 = fmaf(__shfl_sync(0xffffffffu, A[e][0], hh), wt, b0);
                b1 = fmaf(__shfl_sync(0xffffffffu, A[e][1], hh), wt, b1);
                b2 = fmaf(__shfl_sync(0xffffffffu, A[e][2], hh), wt, b2);
            }
            float nr = sqrtf(fmaf(b0,b0,fmaf(b1,b1,b2*b2)) + 1e-8f);
            float gt = 1.f / (1.f + __expf(-nr));
            bool ok = e ? ok1 : ok0;
            long n = e ? n1 : n0;
            if (ok) {
                float* o = g_t4 + n * 496;
                o[3*lane+0]=b0*gt; o[3*lane+1]=b1*gt; o[3*lane+2]=b2*gt;
                float (*acc)[4] = e ? acc1 : acc0;
                float* ta = e ? t1a : t0a;
#pragma unroll
                for (int g = 0; g < 3; g++) {
                    float4 ov;
                    ov.x = fmaxf(acc[g][0], 0.f);
                    ov.y = fmaxf(acc[g][1], 0.f);
                    ov.z = fmaxf(acc[g][2], 0.f);
                    ov.w = fmaxf(acc[g][3], 0.f);
                    *(float4*)(o + 96 + 4*lane + 128*g) = ov;
                }
                if (lane < 4) {
                    float4 ov;
                    ov.x = fmaxf(ta[0], 0.f);
                    ov.y = fmaxf(ta[1], 0.f);
                    ov.z = fmaxf(ta[2], 0.f);
                    ov.w = fmaxf(ta[3], 0.f);
                    *(float4*)(o + 96 + 384 + 4*lane) = ov;
                }
            }
        }
        __syncwarp();
    }
}

// =================================================================
// Kernel 4: final — 512 threads, float4 weight loads (contiguous cols)
// =================================================================
#define F_W 43200
#define F_SMEM ((F_W + 16*864) * 4)   // 228096 B

__global__ __launch_bounds__(512, 1)
void final_kernel(const int* __restrict__ maskV,
                  const float* __restrict__ Wh5, const float* __restrict__ Wv5,
                  const float* __restrict__ Ws5, const float* __restrict__ bs5,
                  const float* __restrict__ lng, const float* __restrict__ lnb,
                  float* __restrict__ out)
{
    extern __shared__ float sm[];
    const int tid = threadIdx.x, w = tid >> 5, lane = tid & 31;
    for (int i = tid; i < F_W; i += 512) sm[i] = __ldg(&Ws5[i]);
    __syncthreads();
    float* xw = sm + F_W + w * 864;
    const int ll = lane < 24 ? lane : 24;   // clamped load lane (cols 4*ll..4*ll+3 <= 99)

    for (long base = (long)blockIdx.x * 32; base < NODES; base += (long)gridDim.x * 32) {
        long n0 = base + w*2, n1 = n0 + 1;
        bool ok0 = n0 < NODES, ok1 = n1 < NODES;
        const float* t0 = g_t4 + (ok0 ? n0 : 0) * 496;
        const float* t1 = g_t4 + (ok1 ? n1 : 0) * 496;

        float A[2][3], vn[2];
#pragma unroll
        for (int e = 0; e < 2; e++) {
            const float* t = e ? t1 : t0;
            float a0=0.f, a1=0.f, a2=0.f;
#pragma unroll
            for (int i = 0; i < 32; i++) {
                float wt = __ldg(&Wh5[i*32 + lane]);
                a0 = fmaf(t[3*i+0], wt, a0);
                a1 = fmaf(t[3*i+1], wt, a1);
                a2 = fmaf(t[3*i+2], wt, a2);
            }
            A[e][0]=a0; A[e][1]=a1; A[e][2]=a2;
            vn[e] = sqrtf(fmaf(a0,a0,fmaf(a1,a1,a2*a2)) + 1e-8f);
        }
        for (int t = lane; t < 400; t += 32) { xw[t] = t0[96+t]; xw[432+t] = t1[96+t]; }
        xw[400+lane] = vn[0]; xw[832+lane] = vn[1];
        __syncwarp();

        // columns: lane owns j = 4*lane .. 4*lane+3 (lane < 25)
        float acc0[4], acc1[4];
        {
            const float4 bv = *(const float4*)(bs5 + 4*ll);
            acc0[0]=bv.x; acc0[1]=bv.y; acc0[2]=bv.z; acc0[3]=bv.w;
            acc1[0]=bv.x; acc1[1]=bv.y; acc1[2]=bv.z; acc1[3]=bv.w;
        }
        const float4* x0 = (const float4*)xw;
        const float4* x1 = (const float4*)(xw + 432);
#pragma unroll 2
        for (int i4 = 0; i4 < 108; i4++) {
            float4 va = x0[i4], vb = x1[i4];
            const float* wr = sm + i4 * 400;
#pragma unroll
            for (int q = 0; q < 4; q++) {
                float fa = f4c(va,q), fb = f4c(vb,q);
                const float4 wv = *(const float4*)(wr + q * 100 + 4*ll);
                acc0[0] = fmaf(fa, wv.x, acc0[0]);
                acc0[1] = fmaf(fa, wv.y, acc0[1]);
                acc0[2] = fmaf(fa, wv.z, acc0[2]);
                acc0[3] = fmaf(fa, wv.w, acc0[3]);
                acc1[0] = fmaf(fb, wv.x, acc1[0]);
                acc1[1] = fmaf(fb, wv.y, acc1[1]);
                acc1[2] = fmaf(fb, wv.z, acc1[2]);
                acc1[3] = fmaf(fb, wv.w, acc1[3]);
            }
        }

        float Bv[2][3];
        const int lc = lane & 15;
#pragma unroll
        for (int e = 0; e < 2; e++) {
            float b0=0.f, b1=0.f, b2=0.f;
#pragma unroll
            for (int hh = 0; hh < 32; hh++) {
                float wt = __ldg(&Wv5[hh*16 + lc]);
                b0 = fmaf(__shfl_sync(0xffffffffu, A[e][0], hh), wt, b0);
                b1 = fmaf(__shfl_sync(0xffffffffu, A[e][1], hh), wt, b1);
                b2 = fmaf(__shfl_sync(0xffffffffu, A[e][2], hh), wt, b2);
            }
            Bv[e][0]=b0; Bv[e][1]=b1; Bv[e][2]=b2;
        }

#pragma unroll
        for (int e = 0; e < 2; e++) {
            bool ok = e ? ok1 : ok0;
            long n = e ? n1 : n0;
            const float* hm = g_hm + (ok ? n : 0) * DIM;
            const float* acc = e ? acc1 : acc0;

            float v0=0.f, v1=0.f, v2=0.f, q=0.f;
            if (lane < 16) {
                v0 = hm[3*lane+0] + Bv[e][0];
                v1 = hm[3*lane+1] + Bv[e][1];
                v2 = hm[3*lane+2] + Bv[e][2];
                q = fmaf(v0,v0,fmaf(v1,v1,v2*v2));
            }
#pragma unroll
            for (int o = 16; o; o >>= 1) q += __shfl_xor_sync(0xffffffffu, q, o);
            float dinv = rsqrtf(q * (1.f/16.f) + 1e-8f);

            float s[4]; float sum = 0.f, sq = 0.f;
#pragma unroll
            for (int jj = 0; jj < 4; jj++) {
                int j = 4*lane + jj;
                s[jj] = (lane < 25) ? (hm[48+j] + acc[jj]) : 0.f;
                sum += s[jj]; sq = fmaf(s[jj], s[jj], sq);
            }
#pragma unroll
            for (int o = 16; o; o >>= 1) {
                sum += __shfl_xor_sync(0xffffffffu, sum, o);
                sq  += __shfl_xor_sync(0xffffffffu, sq,  o);
            }
            float mu  = sum * 0.01f;
            float var = sq * 0.01f - mu*mu;
            float inv = rsqrtf(var + 1e-5f);

            if (ok) {
                float m = (float)__ldg(&maskV[n]);
                float* o = out + n * DIM;
                if (lane < 16) {
                    o[3*lane+0] = m * v0 * dinv;
                    o[3*lane+1] = m * v1 * dinv;
                    o[3*lane+2] = m * v2 * dinv;
                }
                if (lane < 25) {
#pragma unroll
                    for (int jj = 0; jj < 4; jj++) {
                        int j = 4*lane + jj;
                        o[48+j] = m * ((s[jj]-mu)*inv*__ldg(&lng[j]) + __ldg(&lnb[j]));
                    }
                }
            }
        }
        __syncwarp();
    }
}

// =================================================================
extern "C" void kernel_launch(void* const* d_in, const int* in_sizes, int n_in,
                              void* d_out, int out_size)
{
    const float* hV    = (const float*)d_in[0];
    const float* hM    = (const float*)d_in[1];
    const int*   maskV = (const int*)  d_in[2];
    const int*   maskA = (const int*)  d_in[3];
    const float* Wh1 = (const float*)d_in[4];
    const float* Wv1 = (const float*)d_in[5];
    const float* Ws1 = (const float*)d_in[6];
    const float* bs1 = (const float*)d_in[7];
    const float* Wh2 = (const float*)d_in[8];
    const float* Wv2 = (const float*)d_in[9];
    const float* Ws2 = (const float*)d_in[10];
    const float* bs2 = (const float*)d_in[11];
    const float* Wh3 = (const float*)d_in[12];
    const float* Wv3 = (const float*)d_in[13];
    const float* Ws3 = (const float*)d_in[14];
    const float* bs3 = (const float*)d_in[15];
    const float* Wh4 = (const float*)d_in[16];
    const float* Wv4 = (const float*)d_in[17];
    const float* Ws4 = (const float*)d_in[18];
    const float* bs4 = (const float*)d_in[19];
    const float* Wh5 = (const float*)d_in[20];
    const float* Wv5 = (const float*)d_in[21];
    const float* Ws5 = (const float*)d_in[22];
    const float* bs5 = (const float*)d_in[23];
    const float* ln0g = (const float*)d_in[24];
    const float* ln0b = (const float*)d_in[25];
    const float* ln1g = (const float*)d_in[26];
    const float* ln1b = (const float*)d_in[27];

    static int attr_done = 0;
    if (!attr_done) {
        cudaFuncSetAttribute(pre_kernel,
                             cudaFuncAttributeMaxDynamicSharedMemorySize, PRE_SMEM);
        cudaFuncSetAttribute(edge_kernel,
                             cudaFuncAttributeMaxDynamicSharedMemorySize, EDGE_SMEM);
        cudaFuncSetAttribute(gvp4_kernel,
                             cudaFuncAttributeMaxDynamicSharedMemorySize, G4_SMEM);
        cudaFuncSetAttribute(final_kernel,
                             cudaFuncAttributeMaxDynamicSharedMemorySize, F_SMEM);
        attr_done = 1;
    }

    pre_kernel <<<148, 256, PRE_SMEM >>>(hV, Wh1, Ws1, bs1);
    edge_kernel<<<148, 512, EDGE_SMEM>>>(hM, maskA, hV, ln0g, ln0b,
                                         Wh1, Wv1, Ws1,
                                         Wh2, Wv2, Ws2, bs2,
                                         Wh3, Wv3, Ws3, bs3);
    gvp4_kernel<<<148, 512, G4_SMEM>>>(Wh4, Wv4, Ws4, bs4);
    final_kernel<<<148, 512, F_SMEM>>>(maskV, Wh5, Wv5, Ws5, bs5, ln1g, ln1b,
                                       (float*)d_out);
}

// round 16
// speedup vs baseline: 1.0489x; 1.0489x over previous
#include <cuda_runtime.h>
#include <cuda_bf16.h>
#include <math.h>

#define BB 2
#define NN 8192
#define KK 30
#define NODES (BB*NN)
#define DIM 148

// ---------------- scratch ----------------
__device__ float g_vhV[NODES * 96];
__device__ float g_sV1[NODES * 100];
__device__ float g_hm [NODES * DIM];
__device__ float g_t4 [NODES * 496];

__device__ __forceinline__ float f4c(const float4& v, int q) {
    return q == 0 ? v.x : q == 1 ? v.y : q == 2 ? v.z : v.w;
}
__device__ __forceinline__ unsigned tf32u(float f) {
    unsigned u;
    asm("cvt.rna.tf32.f32 %0, %1;" : "=r"(u) : "f"(f));
    return u;
}
__device__ __forceinline__ float tf32f(float f) { return __uint_as_float(tf32u(f)); }

__device__ __forceinline__ void mma8(float c[4], const unsigned a[4], unsigned b0, unsigned b1) {
    asm volatile(
        "mma.sync.aligned.m16n8k8.row.col.f32.tf32.tf32.f32 "
        "{%0,%1,%2,%3}, {%4,%5,%6,%7}, {%8,%9}, {%0,%1,%2,%3};"
        : "+f"(c[0]), "+f"(c[1]), "+f"(c[2]), "+f"(c[3])
        : "r"(a[0]), "r"(a[1]), "r"(a[2]), "r"(a[3]), "r"(b0), "r"(b1));
}

// =================================================================
// Kernel 0: per-node precompute
// =================================================================
#define P_W 10000
#define PRE_SMEM ((P_W + 8*200) * 4)

__global__ __launch_bounds__(256, 1)
void pre_kernel(const float* __restrict__ hV,
                const float* __restrict__ Wh1,
                const float* __restrict__ Ws1,
                const float* __restrict__ bs1)
{
    extern __shared__ float sm[];
    const int tid = threadIdx.x, w = tid >> 5, lane = tid & 31;
    for (int i = tid; i < P_W; i += 256) sm[i] = __ldg(&Ws1[i]);
    __syncthreads();
    float* xw = sm + P_W + w * 200;

    for (long base = (long)blockIdx.x * 16; base < NODES; base += (long)gridDim.x * 16) {
        long n0 = base + w * 2, n1 = n0 + 1;
        bool ok0 = n0 < NODES, ok1 = n1 < NODES;
        const float* hv0 = hV + (ok0 ? n0 : 0) * DIM;
        const float* hv1 = hV + (ok1 ? n1 : 0) * DIM;

#pragma unroll
        for (int e = 0; e < 2; e++) {
            const float* hv = e ? hv1 : hv0;
            float a0 = 0.f, a1 = 0.f, a2 = 0.f;
#pragma unroll
            for (int i = 0; i < 16; i++) {
                float wt = __ldg(&Wh1[i * 32 + lane]);
                a0 = fmaf(hv[3*i+0], wt, a0);
                a1 = fmaf(hv[3*i+1], wt, a1);
                a2 = fmaf(hv[3*i+2], wt, a2);
            }
            bool ok = e ? ok1 : ok0;
            long n = e ? n1 : n0;
            if (ok) {
                g_vhV[n*96 + lane*3 + 0] = a0;
                g_vhV[n*96 + lane*3 + 1] = a1;
                g_vhV[n*96 + lane*3 + 2] = a2;
            }
        }

        for (int t = lane; t < 100; t += 32) { xw[t] = hv0[48+t]; xw[100+t] = hv1[48+t]; }
        __syncwarp();

        int jc[4]; float a0[4], a1[4];
#pragma unroll
        for (int jj = 0; jj < 4; jj++) {
            int j = jj*32 + lane; jc[jj] = j < 100 ? j : 99;
            float v = __ldg(&bs1[jc[jj]]);
            a0[jj] = v; a1[jj] = v;
        }
        const float4* x0 = (const float4*)xw;
        const float4* x1 = (const float4*)(xw + 100);
#pragma unroll 2
        for (int i4 = 0; i4 < 25; i4++) {
            float4 va = x0[i4], vb = x1[i4];
            const float* wr = sm + i4 * 400;
#pragma unroll
            for (int q = 0; q < 4; q++) {
                float fa = f4c(va,q), fb = f4c(vb,q);
                const float* wq = wr + q * 100;
#pragma unroll
                for (int jj = 0; jj < 4; jj++) {
                    float wt = wq[jc[jj]];
                    a0[jj] = fmaf(fa, wt, a0[jj]);
                    a1[jj] = fmaf(fb, wt, a1[jj]);
                }
            }
        }
#pragma unroll
        for (int jj = 0; jj < 4; jj++) {
            int j = jj*32 + lane;
            if (j < 100) {
                if (ok0) g_sV1[n0*100 + j] = a0[jj];
                if (ok1) g_sV1[n1*100 + j] = a1[jj];
            }
        }
        __syncwarp();
    }
}

// =================================================================
// Edge kernel: s-GEMM spread over 13 warps (1 n-tile each)
// =================================================================
#define O_W1    0        // [136][104] tf32 (Ws1 rows 100..231)
#define O_W2    14144    // [120][104]
#define O_W3    26624    // [120][104]
#define O_WH1S  39104    // [16][40]
#define O_WV1S  39744    // [32][24]
#define O_WH2S  40512    // [16][24]
#define O_WV2S  40896
#define O_WH3S  41280
#define O_WV3S  41664
#define O_BS2   42048    // 100
#define O_BS3   42148    // 100
#define O_PVH   42248    // 96
#define O_PRS   42344    // 100
#define O_ACC   42444    // 148
#define O_MK    42592    // 32
#define O_VA    42624    // [96][20]
#define O_VB    44544    // [96][36]
#define O_X1    48000    // [32][140] (X3 aliases, stride 124)
#define O_X2    52480    // [32][124] (z/zv reuse)
#define O_HV    56448    // 148
#define SM_FLOATS 56596
#define EDGE_SMEM (SM_FLOATS * 4)

#define XS1 140
#define XS2 124
#define WS  104
#define VAS 20
#define VBS 36

// 13-warp s-stage MMA: warp w (0..12) handles n-tile w, m-tiles {0,1}
__device__ __forceinline__ void mma_stage13(const unsigned* __restrict__ X, int XS,
                                            const unsigned* __restrict__ Wm, int KT,
                                            int gid, int tig, int w, float C[2][4])
{
    const int col = 8*w + gid;
#pragma unroll 2
    for (int kt = 0; kt < KT; kt++) {
        const int k0 = kt * 8;
        unsigned a[2][4];
#pragma unroll
        for (int mt = 0; mt < 2; mt++) {
            const unsigned* xr = X + (16*mt + gid)*XS + k0 + tig;
            a[mt][0] = xr[0];
            a[mt][1] = xr[8*XS];
            a[mt][2] = xr[4];
            a[mt][3] = xr[8*XS + 4];
        }
        const unsigned* wr = Wm + (k0 + tig)*WS;
        unsigned b0 = wr[col], b1 = wr[4*WS + col];
        mma8(C[0], a[0], b0, b1);
        mma8(C[1], a[1], b0, b1);
    }
}

__device__ __forceinline__ void store_stage13(float* __restrict__ Xo, int XSo,
                                              const float* __restrict__ addend,
                                              const float C[2][4],
                                              int gid, int tig, int w)
{
#pragma unroll
    for (int mt = 0; mt < 2; mt++)
#pragma unroll
    for (int r = 0; r < 4; r++) {
        int edge = 16*mt + gid + ((r >> 1) << 3);
        int n = 8*w + 2*tig + (r & 1);
        if (edge < 30 && n < 100)
            Xo[edge*XSo + n] = tf32f(fmaxf(C[mt][r] + addend[n], 0.f));
    }
}

__device__ __forceinline__ void mma_tile(const unsigned* __restrict__ A, int AS,
                                         const unsigned* __restrict__ Bw, int BS,
                                         int KT, int mt, int nt,
                                         int gid, int tig, float C[4])
{
#pragma unroll 2
    for (int kt = 0; kt < KT; kt++) {
        const unsigned* xr = A + (16*mt + gid)*AS + kt*8 + tig;
        unsigned a[4] = { xr[0], xr[8*AS], xr[4], xr[8*AS + 4] };
        const unsigned* wr = Bw + (kt*8 + tig)*BS;
        mma8(C, a, wr[8*nt + gid], wr[4*BS + 8*nt + gid]);
    }
}

__global__ __launch_bounds__(512, 1)
void edge_kernel(const float* __restrict__ hM, const int* __restrict__ maskA,
                 const float* __restrict__ hV,
                 const float* __restrict__ lng, const float* __restrict__ lnb,
                 const float* __restrict__ Wh1, const float* __restrict__ Wv1,
                 const float* __restrict__ Ws1,
                 const float* __restrict__ Wh2, const float* __restrict__ Wv2,
                 const float* __restrict__ Ws2, const float* __restrict__ bs2,
                 const float* __restrict__ Wh3, const float* __restrict__ Wv3,
                 const float* __restrict__ Ws3, const float* __restrict__ bs3)
{
    extern __shared__ float sm[];
    unsigned* usm = (unsigned*)sm;
    const int tid = threadIdx.x, w = tid >> 5, lane = tid & 31;
    const int gid = lane >> 2, tig = lane & 3;

    // ---- one-time weight fills ----
    for (int i = tid; i < 136*WS; i += 512) {
        int k = i / WS, n = i - k*WS;
        sm[O_W1+i] = (k < 132 && n < 100) ? tf32f(__ldg(&Ws1[(100+k)*100 + n])) : 0.f;
    }
    for (int i = tid; i < 120*WS; i += 512) {
        int k = i / WS, n = i - k*WS;
        sm[O_W2+i] = (k < 116 && n < 100) ? tf32f(__ldg(&Ws2[k*100 + n])) : 0.f;
        sm[O_W3+i] = (k < 116 && n < 100) ? tf32f(__ldg(&Ws3[k*100 + n])) : 0.f;
    }
    for (int i = tid; i < 512; i += 512) {
        int k = i >> 5, n = i & 31;
        sm[O_WH1S + k*40 + n] = tf32f(__ldg(&Wh1[(16+k)*32 + n]));
    }
    if (tid < 512) {
        int k = tid >> 4, n = tid & 15;
        sm[O_WV1S + k*24 + n] = tf32f(__ldg(&Wv1[k*16 + n]));
    }
    if (tid < 256) {
        int k = tid >> 4, n = tid & 15;
        sm[O_WH2S + k*24 + n] = tf32f(__ldg(&Wh2[tid]));
        sm[O_WV2S + k*24 + n] = tf32f(__ldg(&Wv2[tid]));
        sm[O_WH3S + k*24 + n] = tf32f(__ldg(&Wh3[tid]));
        sm[O_WV3S + k*24 + n] = tf32f(__ldg(&Wv3[tid]));
    }
    if (tid < 100) { sm[O_BS2+tid] = __ldg(&bs2[tid]); sm[O_BS3+tid] = __ldg(&bs3[tid]); }
    for (int i = tid; i < 32*XS2; i += 512) sm[O_X2+i] = 0.f;
    for (int i = tid; i < 2*XS1;  i += 512) sm[O_X1 + 30*XS1 + i] = 0.f;
    for (int i = tid; i < 30*8;   i += 512) sm[O_X1 + (i>>3)*XS1 + 132 + (i&7)] = 0.f;

    // ---- prefetch setup ----
    int soff[9]; bool sval[9];
#pragma unroll
    for (int r = 0; r < 9; r++) {
        int idx = tid + r*512;
        sval[r] = idx < KK*DIM;
        int ii = sval[r] ? idx : 0;
        int e = ii / DIM, t = ii - e*DIM;
        soff[r] = (t < 48) ? (O_VA + (3*e + t%3)*VAS + t/3)
                           : (O_X1 + e*XS1 + (t-48));
    }
    float R[9]; int mkR = 0; float pvhR = 0.f, prsR = 0.f, hvR = 0.f;

    {   // prologue prefetch
        long n = blockIdx.x;
        const float* src = hM + n*KK*DIM;
#pragma unroll
        for (int r = 0; r < 9; r++) if (sval[r]) R[r] = __ldg(&src[tid + r*512]);
        if (tid < 30)  mkR  = __ldg(&maskA[n*KK + tid]);
        if (tid < 96)  pvhR = g_vhV[n*96 + tid];
        if (tid < 100) prsR = g_sV1[n*100 + tid];
        if (tid < 148) hvR  = __ldg(&hV[n*DIM + tid]);
    }
    __syncthreads();

    for (long node = blockIdx.x; node < NODES; node += gridDim.x) {
        // ---- P0: scatter prefetched data ----
#pragma unroll
        for (int r = 0; r < 9; r++) if (sval[r]) sm[soff[r]] = tf32f(R[r]);
        if (tid < 30)  sm[O_MK + tid]  = (float)mkR;
        if (tid < 96)  sm[O_PVH + tid] = pvhR;
        if (tid < 100) sm[O_PRS + tid] = prsR;
        if (tid < 148) sm[O_HV + tid]  = hvR;
        __syncthreads();

        // prefetch next node
        {
            long nn = node + gridDim.x;
            long n = (nn < NODES) ? nn : node;
            const float* src = hM + n*KK*DIM;
#pragma unroll
            for (int r = 0; r < 9; r++) if (sval[r]) R[r] = __ldg(&src[tid + r*512]);
            if (tid < 30)  mkR  = __ldg(&maskA[n*KK + tid]);
            if (tid < 96)  pvhR = g_vhV[n*96 + tid];
            if (tid < 100) prsR = g_sV1[n*100 + tid];
            if (tid < 148) hvR  = __ldg(&hV[n*DIM + tid]);
        }

        // ---- P1: vh1 MMA (24 tiles) ----
        for (int t = w; t < 24; t += 16) {
            int mt = t % 6, nt = t / 6;
            float C[4] = {};
            mma_tile(usm + O_VA, VAS, usm + O_WH1S, 40, 2, mt, nt, gid, tig, C);
#pragma unroll
            for (int r = 0; r < 4; r++) {
                int row = 16*mt + gid + 8*(r>>1);
                int n = 8*nt + 2*tig + (r&1);
                sm[O_VB + row*VBS + n] = tf32f(C[r] + sm[O_PVH + n*3 + (row%3)]);
            }
        }
        __syncthreads();

        // ---- P2: vn1 -> X1 cols 100..131 ----
        for (int v = tid; v < 960; v += 512) {
            int e = v >> 5, h = v & 31;
            float x0 = sm[O_VB + (3*e+0)*VBS + h];
            float x1 = sm[O_VB + (3*e+1)*VBS + h];
            float x2 = sm[O_VB + (3*e+2)*VBS + h];
            sm[O_X1 + e*XS1 + 100 + h] = tf32f(sqrtf(fmaf(x0,x0,fmaf(x1,x1,x2*x2)) + 1e-8f));
        }
        __syncthreads();

        // ---- P3: s1 MMA (w<13) || v1 MMA (w>=13) ----
        if (w < 13) {
            float C[2][4] = {};
            mma_stage13(usm + O_X1, XS1, usm + O_W1, 17, gid, tig, w, C);
            store_stage13(sm + O_X2, XS2, sm + O_PRS, C, gid, tig, w);
        } else {
            for (int t = w - 13; t < 12; t += 3) {
                int mt = t % 6, nt = t / 6;
                float C[4] = {};
                mma_tile(usm + O_VB, VBS, usm + O_WV1S, 24, 4, mt, nt, gid, tig, C);
#pragma unroll
                for (int r = 0; r < 4; r++) {
                    int row = 16*mt + gid + 8*(r>>1);
                    int n = 8*nt + 2*tig + (r&1);
                    sm[O_VA + row*VAS + n] = C[r];
                }
            }
        }
        __syncthreads();

        // ---- P4: gate v1 ----
        if (tid < 480) {
            int e = tid >> 4, h = tid & 15;
            float x0 = sm[O_VA + (3*e+0)*VAS + h];
            float x1 = sm[O_VA + (3*e+1)*VAS + h];
            float x2 = sm[O_VA + (3*e+2)*VAS + h];
            float nr = sqrtf(fmaf(x0,x0,fmaf(x1,x1,x2*x2)) + 1e-8f);
            float g = 1.f / (1.f + __expf(-nr));
            sm[O_VA + (3*e+0)*VAS + h] = tf32f(x0*g);
            sm[O_VA + (3*e+1)*VAS + h] = tf32f(x1*g);
            sm[O_VA + (3*e+2)*VAS + h] = tf32f(x2*g);
        }
        __syncthreads();

        // ---- P5: vh2 MMA (12 tiles) ----
        for (int t = w; t < 12; t += 16) {
            int mt = t % 6, nt = t / 6;
            float C[4] = {};
            mma_tile(usm + O_VA, VAS, usm + O_WH2S, 24, 2, mt, nt, gid, tig, C);
#pragma unroll
            for (int r = 0; r < 4; r++) {
                int row = 16*mt + gid + 8*(r>>1);
                int n = 8*nt + 2*tig + (r&1);
                sm[O_VB + row*VBS + n] = tf32f(C[r]);
            }
        }
        __syncthreads();

        // ---- P6: vn2 -> X2 cols 100..115 ----
        if (tid < 480) {
            int e = tid >> 4, h = tid & 15;
            float x0 = sm[O_VB + (3*e+0)*VBS + h];
            float x1 = sm[O_VB + (3*e+1)*VBS + h];
            float x2 = sm[O_VB + (3*e+2)*VBS + h];
            sm[O_X2 + e*XS2 + 100 + h] = tf32f(sqrtf(fmaf(x0,x0,fmaf(x1,x1,x2*x2)) + 1e-8f));
        }
        __syncthreads();

        // ---- P7: s2 MMA (w<13) || v2 MMA (w>=13) ----
        if (w < 13) {
            float C[2][4] = {};
            mma_stage13(usm + O_X2, XS2, usm + O_W2, 15, gid, tig, w, C);
            store_stage13(sm + O_X1, XS2, sm + O_BS2, C, gid, tig, w);   // X3 = X1 space
        } else {
            for (int t = w - 13; t < 12; t += 3) {
                int mt = t % 6, nt = t / 6;
                float C[4] = {};
                mma_tile(usm + O_VB, VBS, usm + O_WV2S, 24, 2, mt, nt, gid, tig, C);
#pragma unroll
                for (int r = 0; r < 4; r++) {
                    int row = 16*mt + gid + 8*(r>>1);
                    int n = 8*nt + 2*tig + (r&1);
                    sm[O_VA + row*VAS + n] = C[r];
                }
            }
        }
        __syncthreads();

        // ---- P8: gate v2 ----
        if (tid < 480) {
            int e = tid >> 4, h = tid & 15;
            float x0 = sm[O_VA + (3*e+0)*VAS + h];
            float x1 = sm[O_VA + (3*e+1)*VAS + h];
            float x2 = sm[O_VA + (3*e+2)*VAS + h];
            float nr = sqrtf(fmaf(x0,x0,fmaf(x1,x1,x2*x2)) + 1e-8f);
            float g = 1.f / (1.f + __expf(-nr));
            sm[O_VA + (3*e+0)*VAS + h] = tf32f(x0*g);
            sm[O_VA + (3*e+1)*VAS + h] = tf32f(x1*g);
            sm[O_VA + (3*e+2)*VAS + h] = tf32f(x2*g);
        }
        __syncthreads();

        // ---- P9: vh3 MMA ----
        for (int t = w; t < 12; t += 16) {
            int mt = t % 6, nt = t / 6;
            float C[4] = {};
            mma_tile(usm + O_VA, VAS, usm + O_WH3S, 24, 2, mt, nt, gid, tig, C);
#pragma unroll
            for (int r = 0; r < 4; r++) {
                int row = 16*mt + gid + 8*(r>>1);
                int n = 8*nt + 2*tig + (r&1);
                sm[O_VB + row*VBS + n] = tf32f(C[r]);
            }
        }
        __syncthreads();

        // ---- P10: vn3 -> X3 cols 100..115 ----
        if (tid < 480) {
            int e = tid >> 4, h = tid & 15;
            float x0 = sm[O_VB + (3*e+0)*VBS + h];
            float x1 = sm[O_VB + (3*e+1)*VBS + h];
            float x2 = sm[O_VB + (3*e+2)*VBS + h];
            sm[O_X1 + e*XS2 + 100 + h] = tf32f(sqrtf(fmaf(x0,x0,fmaf(x1,x1,x2*x2)) + 1e-8f));
        }
        __syncthreads();

        // ---- P11: linearized stage 3 — masked sums ----
        if (tid < 116) {
            float s = 0.f;
#pragma unroll 5
            for (int e = 0; e < 30; e++)
                s = fmaf(sm[O_MK + e], sm[O_X1 + e*XS2 + tid], s);
            sm[O_X2 + tid] = s;
        } else if (tid >= 128 && tid < 176) {
            int i = tid - 128;
            int h = i / 3, c = i - 3*h;
            float s = 0.f;
#pragma unroll 5
            for (int e = 0; e < 30; e++)
                s = fmaf(sm[O_MK + e], sm[O_VB + (3*e+c)*VBS + h], s);
            sm[O_X2 + 128 + i] = s;
        }
        __syncthreads();

        // ---- P12: tiny matvecs ----
        if (tid < 100) {
            float acc = 0.f;
#pragma unroll 4
            for (int k = 0; k < 116; k++)
                acc = fmaf(sm[O_X2 + k], sm[O_W3 + k*WS + tid], acc);
            sm[O_ACC + 48 + tid] = acc;
        } else if (tid >= 128 && tid < 176) {
            int i = tid - 128;
            int o = i / 3, c = i - 3*o;
            float acc = 0.f;
#pragma unroll
            for (int h = 0; h < 16; h++)
                acc = fmaf(sm[O_X2 + 128 + h*3 + c], sm[O_WV3S + h*24 + o], acc);
            sm[O_ACC + 3*o + c] = acc;
        }
        __syncthreads();

        // ---- P13: ln0 -> g_hm ----
        if (w == 0) {
            float smk = (lane < 30) ? sm[O_MK + lane] : 0.f;
#pragma unroll
            for (int o = 16; o; o >>= 1) smk += __shfl_xor_sync(0xffffffffu, smk, o);

            const float inv30 = 1.f / 30.f;
            float v0=0.f, v1=0.f, v2=0.f, q=0.f;
            if (lane < 16) {
                v0 = sm[O_HV + 3*lane+0] + sm[O_ACC + 3*lane+0] * inv30;
                v1 = sm[O_HV + 3*lane+1] + sm[O_ACC + 3*lane+1] * inv30;
                v2 = sm[O_HV + 3*lane+2] + sm[O_ACC + 3*lane+2] * inv30;
                q = fmaf(v0,v0,fmaf(v1,v1,v2*v2));
            }
#pragma unroll
            for (int o = 16; o; o >>= 1) q += __shfl_xor_sync(0xffffffffu, q, o);
            float dinv = rsqrtf(q * (1.f/16.f) + 1e-8f);

            float s[4]; float sum = 0.f, sq = 0.f;
#pragma unroll
            for (int jj = 0; jj < 4; jj++) {
                int j = jj*32 + lane;
                s[jj] = (j < 100)
                    ? (sm[O_HV + 48+j] + (sm[O_ACC + 48 + j] + sm[O_BS3+j]*smk) * inv30) : 0.f;
                sum += s[jj]; sq = fmaf(s[jj], s[jj], sq);
            }
#pragma unroll
            for (int o = 16; o; o >>= 1) {
                sum += __shfl_xor_sync(0xffffffffu, sum, o);
                sq  += __shfl_xor_sync(0xffffffffu, sq,  o);
            }
            float mu  = sum * 0.01f;
            float var = sq * 0.01f - mu*mu;
            float inv = rsqrtf(var + 1e-5f);

            float* o = g_hm + (long)node * DIM;
            if (lane < 16) {
                o[3*lane+0] = v0*dinv; o[3*lane+1] = v1*dinv; o[3*lane+2] = v2*dinv;
            }
#pragma unroll
            for (int jj = 0; jj < 4; jj++) {
                int j = jj*32 + lane;
                if (j < 100) o[48+j] = (s[jj]-mu)*inv*__ldg(&lng[j]) + __ldg(&lnb[j]);
            }
        }
        __syncthreads();
    }
}

// =================================================================
// Kernel 3: gvp4 — R13 form (512 threads, 2 nodes/warp)
// =================================================================
#define G4_W 52800
#define G4_SMEM ((G4_W + 16*264) * 4)   // 228096 B

__global__ __launch_bounds__(512, 1)
void gvp4_kernel(const float* __restrict__ Wh4, const float* __restrict__ Wv4,
                 const float* __restrict__ Ws4, const float* __restrict__ bs4)
{
    extern __shared__ float sm[];
    const int tid = threadIdx.x, w = tid >> 5, lane = tid & 31;
    for (int i = tid; i < G4_W; i += 512) sm[i] = __ldg(&Ws4[i]);
    __syncthreads();
    float* xw = sm + G4_W + w * 264;

    for (long base = (long)blockIdx.x * 32; base < NODES; base += (long)gridDim.x * 32) {
        long n0 = base + w*2, n1 = n0 + 1;
        bool ok0 = n0 < NODES, ok1 = n1 < NODES;
        const float* h0 = g_hm + (ok0 ? n0 : 0) * DIM;
        const float* h1 = g_hm + (ok1 ? n1 : 0) * DIM;

        float A[2][3], vn[2];
#pragma unroll
        for (int e = 0; e < 2; e++) {
            const float* h = e ? h1 : h0;
            float a0=0.f, a1=0.f, a2=0.f;
#pragma unroll
            for (int i = 0; i < 16; i++) {
                float wt = __ldg(&Wh4[i*32 + lane]);
                a0 = fmaf(h[3*i+0], wt, a0);
                a1 = fmaf(h[3*i+1], wt, a1);
                a2 = fmaf(h[3*i+2], wt, a2);
            }
            A[e][0]=a0; A[e][1]=a1; A[e][2]=a2;
            vn[e] = sqrtf(fmaf(a0,a0,fmaf(a1,a1,a2*a2)) + 1e-8f);
        }
        for (int t = lane; t < 100; t += 32) { xw[t] = h0[48+t]; xw[132+t] = h1[48+t]; }
        xw[100+lane] = vn[0]; xw[232+lane] = vn[1];
        __syncwarp();

        float acc0[13], acc1[13];
        int jm[13];
#pragma unroll
        for (int jj = 0; jj < 13; jj++) {
            int j = lane + jj*32; jm[jj] = j < 400 ? j : 399;
            float v = __ldg(&bs4[jm[jj]]);
            acc0[jj] = v; acc1[jj] = v;
        }
        const float4* x0 = (const float4*)xw;
        const float4* x1 = (const float4*)(xw + 132);
        for (int i4 = 0; i4 < 33; i4++) {
            float4 va = x0[i4], vb = x1[i4];
            const float* wr = sm + i4 * 1600;
#pragma unroll
            for (int q = 0; q < 4; q++) {
                float fa = f4c(va,q), fb = f4c(vb,q);
                const float* wq = wr + q * 400;
#pragma unroll
                for (int jj = 0; jj < 13; jj++) {
                    float wt = wq[jm[jj]];
                    acc0[jj] = fmaf(fa, wt, acc0[jj]);
                    acc1[jj] = fmaf(fb, wt, acc1[jj]);
                }
            }
        }
#pragma unroll
        for (int jj = 0; jj < 13; jj++) {
            acc0[jj] = fmaxf(acc0[jj], 0.f);
            acc1[jj] = fmaxf(acc1[jj], 0.f);
        }

#pragma unroll
        for (int e = 0; e < 2; e++) {
            float b0=0.f, b1=0.f, b2=0.f;
#pragma unroll
            for (int hh = 0; hh < 32; hh++) {
                float wt = __ldg(&Wv4[hh*32 + lane]);
                b0 = fmaf(__shfl_sync(0xffffffffu, A[e][0], hh), wt, b0);
                b1 = fmaf(__shfl_sync(0xffffffffu, A[e][1], hh), wt, b1);
                b2 = fmaf(__shfl_sync(0xffffffffu, A[e][2], hh), wt, b2);
            }
            float nr = sqrtf(fmaf(b0,b0,fmaf(b1,b1,b2*b2)) + 1e-8f);
            float gt = 1.f / (1.f + __expf(-nr));
            bool ok = e ? ok1 : ok0;
            long n = e ? n1 : n0;
            if (ok) {
                float* o = g_t4 + n * 496;
                o[3*lane+0]=b0*gt; o[3*lane+1]=b1*gt; o[3*lane+2]=b2*gt;
                float* acc = e ? acc1 : acc0;
#pragma unroll
                for (int jj = 0; jj < 13; jj++) {
                    int j = lane + jj*32;
                    if (j < 400) o[96+j] = acc[jj];
                }
            }
        }
        __syncwarp();
    }
}

// =================================================================
// Kernel 4: final — R13 form (512 threads, 2 nodes/warp)
// =================================================================
#define F_W 43200
#define F_SMEM ((F_W + 16*864) * 4)   // 228096 B

__global__ __launch_bounds__(512, 1)
void final_kernel(const int* __restrict__ maskV,
                  const float* __restrict__ Wh5, const float* __restrict__ Wv5,
                  const float* __restrict__ Ws5, const float* __restrict__ bs5,
                  const float* __restrict__ lng, const float* __restrict__ lnb,
                  float* __restrict__ out)
{
    extern __shared__ float sm[];
    const int tid = threadIdx.x, w = tid >> 5, lane = tid & 31;
    for (int i = tid; i < F_W; i += 512) sm[i] = __ldg(&Ws5[i]);
    __syncthreads();
    float* xw = sm + F_W + w * 864;

    for (long base = (long)blockIdx.x * 32; base < NODES; base += (long)gridDim.x * 32) {
        long n0 = base + w*2, n1 = n0 + 1;
        bool ok0 = n0 < NODES, ok1 = n1 < NODES;
        const float* t0 = g_t4 + (ok0 ? n0 : 0) * 496;
        const float* t1 = g_t4 + (ok1 ? n1 : 0) * 496;

        float A[2][3], vn[2];
#pragma unroll
        for (int e = 0; e < 2; e++) {
            const float* t = e ? t1 : t0;
            float a0=0.f, a1=0.f, a2=0.f;
#pragma unroll
            for (int i = 0; i < 32; i++) {
                float wt = __ldg(&Wh5[i*32 + lane]);
                a0 = fmaf(t[3*i+0], wt, a0);
                a1 = fmaf(t[3*i+1], wt, a1);
                a2 = fmaf(t[3*i+2], wt, a2);
            }
            A[e][0]=a0; A[e][1]=a1; A[e][2]=a2;
            vn[e] = sqrtf(fmaf(a0,a0,fmaf(a1,a1,a2*a2)) + 1e-8f);
        }
        for (int t = lane; t < 400; t += 32) { xw[t] = t0[96+t]; xw[432+t] = t1[96+t]; }
        xw[400+lane] = vn[0]; xw[832+lane] = vn[1];
        __syncwarp();

        float acc0[4], acc1[4];
        int jc[4];
#pragma unroll
        for (int jj = 0; jj < 4; jj++) {
            int j = jj*32 + lane; jc[jj] = j < 100 ? j : 99;
            float v = __ldg(&bs5[jc[jj]]);
            acc0[jj] = v; acc1[jj] = v;
        }
        const float4* x0 = (const float4*)xw;
        const float4* x1 = (const float4*)(xw + 432);
#pragma unroll 2
        for (int i4 = 0; i4 < 108; i4++) {
            float4 va = x0[i4], vb = x1[i4];
            const float* wr = sm + i4 * 400;
#pragma unroll
            for (int q = 0; q < 4; q++) {
                float fa = f4c(va,q), fb = f4c(vb,q);
                const float* wq = wr + q * 100;
#pragma unroll
                for (int jj = 0; jj < 4; jj++) {
                    float wt = wq[jc[jj]];
                    acc0[jj] = fmaf(fa, wt, acc0[jj]);
                    acc1[jj] = fmaf(fb, wt, acc1[jj]);
                }
            }
        }

        float Bv[2][3];
        const int lc = lane & 15;
#pragma unroll
        for (int e = 0; e < 2; e++) {
            float b0=0.f, b1=0.f, b2=0.f;
#pragma unroll
            for (int hh = 0; hh < 32; hh++) {
                float wt = __ldg(&Wv5[hh*16 + lc]);
                b0 = fmaf(__shfl_sync(0xffffffffu, A[e][0], hh), wt, b0);
                b1 = fmaf(__shfl_sync(0xffffffffu, A[e][1], hh), wt, b1);
                b2 = fmaf(__shfl_sync(0xffffffffu, A[e][2], hh), wt, b2);
            }
            Bv[e][0]=b0; Bv[e][1]=b1; Bv[e][2]=b2;
        }

#pragma unroll
        for (int e = 0; e < 2; e++) {
            bool ok = e ? ok1 : ok0;
            long n = e ? n1 : n0;
            const float* hm = g_hm + (ok ? n : 0) * DIM;
            const float* acc = e ? acc1 : acc0;

            float v0=0.f, v1=0.f, v2=0.f, q=0.f;
            if (lane < 16) {
                v0 = hm[3*lane+0] + Bv[e][0];
                v1 = hm[3*lane+1] + Bv[e][1];
                v2 = hm[3*lane+2] + Bv[e][2];
                q = fmaf(v0,v0,fmaf(v1,v1,v2*v2));
            }
#pragma unroll
            for (int o = 16; o; o >>= 1) q += __shfl_xor_sync(0xffffffffu, q, o);
            float dinv = rsqrtf(q * (1.f/16.f) + 1e-8f);

            float s[4]; float sum = 0.f, sq = 0.f;
#pragma unroll
            for (int jj = 0; jj < 4; jj++) {
                int j = jj*32 + lane;
                s[jj] = (j < 100) ? (hm[48+j] + acc[jj]) : 0.f;
                sum += s[jj]; sq = fmaf(s[jj], s[jj], sq);
            }
#pragma unroll
            for (int o = 16; o; o >>= 1) {
                sum += __shfl_xor_sync(0xffffffffu, sum, o);
                sq  += __shfl_xor_sync(0xffffffffu, sq,  o);
            }
            float mu  = sum * 0.01f;
            float var = sq * 0.01f - mu*mu;
            float inv = rsqrtf(var + 1e-5f);

            if (ok) {
                float m = (float)__ldg(&maskV[n]);
                float* o = out + n * DIM;
                if (lane < 16) {
                    o[3*lane+0] = m * v0 * dinv;
                    o[3*lane+1] = m * v1 * dinv;
                    o[3*lane+2] = m * v2 * dinv;
                }
#pragma unroll
                for (int jj = 0; jj < 4; jj++) {
                    int j = jj*32 + lane;
                    if (j < 100)
                        o[48+j] = m * ((s[jj]-mu)*inv*__ldg(&lng[j]) + __ldg(&lnb[j]));
                }
            }
        }
        __syncwarp();
    }
}

// =================================================================
extern "C" void kernel_launch(void* const* d_in, const int* in_sizes, int n_in,
                              void* d_out, int out_size)
{
    const float* hV    = (const float*)d_in[0];
    const float* hM    = (const float*)d_in[1];
    const int*   maskV = (const int*)  d_in[2];
    const int*   maskA = (const int*)  d_in[3];
    const float* Wh1 = (const float*)d_in[4];
    const float* Wv1 = (const float*)d_in[5];
    const float* Ws1 = (const float*)d_in[6];
    const float* bs1 = (const float*)d_in[7];
    const float* Wh2 = (const float*)d_in[8];
    const float* Wv2 = (const float*)d_in[9];
    const float* Ws2 = (const float*)d_in[10];
    const float* bs2 = (const float*)d_in[11];
    const float* Wh3 = (const float*)d_in[12];
    const float* Wv3 = (const float*)d_in[13];
    const float* Ws3 = (const float*)d_in[14];
    const float* bs3 = (const float*)d_in[15];
    const float* Wh4 = (const float*)d_in[16];
    const float* Wv4 = (const float*)d_in[17];
    const float* Ws4 = (const float*)d_in[18];
    const float* bs4 = (const float*)d_in[19];
    const float* Wh5 = (const float*)d_in[20];
    const float* Wv5 = (const float*)d_in[21];
    const float* Ws5 = (const float*)d_in[22];
    const float* bs5 = (const float*)d_in[23];
    const float* ln0g = (const float*)d_in[24];
    const float* ln0b = (const float*)d_in[25];
    const float* ln1g = (const float*)d_in[26];
    const float* ln1b = (const float*)d_in[27];

    static int attr_done = 0;
    if (!attr_done) {
        cudaFuncSetAttribute(pre_kernel,
                             cudaFuncAttributeMaxDynamicSharedMemorySize, PRE_SMEM);
        cudaFuncSetAttribute(edge_kernel,
                             cudaFuncAttributeMaxDynamicSharedMemorySize, EDGE_SMEM);
        cudaFuncSetAttribute(gvp4_kernel,
                             cudaFuncAttributeMaxDynamicSharedMemorySize, G4_SMEM);
        cudaFuncSetAttribute(final_kernel,
                             cudaFuncAttributeMaxDynamicSharedMemorySize, F_SMEM);
        attr_done = 1;
    }

    pre_kernel <<<148, 256, PRE_SMEM >>>(hV, Wh1, Ws1, bs1);
    edge_kernel<<<148, 512, EDGE_SMEM>>>(hM, maskA, hV, ln0g, ln0b,
                                         Wh1, Wv1, Ws1,
                                         Wh2, Wv2, Ws2, bs2,
                                         Wh3, Wv3, Ws3, bs3);
    gvp4_kernel<<<148, 512, G4_SMEM>>>(Wh4, Wv4, Ws4, bs4);
    final_kernel<<<148, 512, F_SMEM>>>(maskV, Wh5, Wv5, Ws5, bs5, ln1g, ln1b,
                                       (float*)d_out);
}